// round 2
// baseline (speedup 1.0000x reference)
#include <cuda_runtime.h>

// RNN: B=4096 sequences, T=1024 steps, H=64 hidden, scalar input, C=5 head.
//   xp[t,b,h] = x[b,t]*w_ih[h] + b_ih[h] + b_hh[h]
//   h_{t+1}[b,i] = tanh(xp[t,b,i] + sum_j h_t[b,j]*w_hh[i,j])
//   out[b,c] = sum_h hT[b,h]*w_head[c,h] + b_head[c]
//
// Strategy: pure-SMEM recurrent kernel, two batches packed per lane via
// fma.rn.f32x2 (sm_100+ packed fp32 FMA, full-rate fp32 pipe).
// 128 CTAs x 32 batches, 128 threads, double-buffered h, 1 barrier/step.

#define BB 4096
#define TT 1024
#define HH 64
#define CC 5
#define NB 32          // batches per CTA
#define NP 16          // batch-pairs per CTA
#define NTHREADS 128
#define TCH 32         // x staging chunk (timesteps)

#define WB_BYTES (32*64*16)        // W dup {w,w}, [unit u][row i] 16B units
#define HB_BYTES (2*32*16*16)      // h, 2 bufs x [unit u][pair p] 16B units
#define XS_BYTES (TCH*NP*8)        // x pairs, [tc][p] float2
#define SMEM_BYTES (WB_BYTES + HB_BYTES + XS_BYTES)

typedef unsigned long long u64;

__device__ __forceinline__ u64 pk2(float lo, float hi) {
    u64 r; asm("mov.b64 %0, {%1,%2};" : "=l"(r) : "f"(lo), "f"(hi)); return r;
}
__device__ __forceinline__ float2 up2(u64 v) {
    float2 f; asm("mov.b64 {%0,%1}, %2;" : "=f"(f.x), "=f"(f.y) : "l"(v)); return f;
}
// d = a*b + c on packed f32x2 (two batch elements per register pair)
__device__ __forceinline__ u64 fma2(u64 a, u64 b, u64 c) {
    u64 d; asm("fma.rn.f32x2 %0, %1, %2, %3;" : "=l"(d) : "l"(a), "l"(b), "l"(c)); return d;
}
__device__ __forceinline__ float ftanh(float xv) {
    // tanh(x) = 1 - 2/(e^{2x}+1); handles saturation via inf/0 naturally.
    float e = __expf(2.0f * xv);
    return 1.0f - __fdividef(2.0f, e + 1.0f);
}

extern "C" __global__ void __launch_bounds__(NTHREADS, 1)
rnn_f32x2_kernel(const float* __restrict__ x,
                 const float* __restrict__ w_ih,
                 const float* __restrict__ b_ih,
                 const float* __restrict__ w_hh,
                 const float* __restrict__ b_hh,
                 const float* __restrict__ w_head,
                 const float* __restrict__ b_head,
                 float* __restrict__ out)
{
    extern __shared__ __align__(16) unsigned char smem_raw[];
    ulonglong2* wb = (ulonglong2*)smem_raw;                       // [u*64 + i]
    ulonglong2* hb = (ulonglong2*)(smem_raw + WB_BYTES);          // [buf*512 + u*16 + p]
    u64*        xs = (u64*)(smem_raw + WB_BYTES + HB_BYTES);      // [tc*NP + p]

    const int tid = threadIdx.x;
    const int b0  = blockIdx.x * NB;
    const int pg  = tid & 7;        // pair group: pairs {pg, pg+8}
    const int rg  = tid >> 3;       // row group: rows {rg, rg+16, rg+32, rg+48}

    // --- stage W duplicated as {w,w}, interleaved [unit][row] for conflict-free loads
    for (int e = tid; e < HH*HH; e += NTHREADS) {
        int i = e >> 6;
        int j = e & 63;
        float w = w_hh[e];
        int u = j >> 1, k = j & 1;
        ((u64*)&wb[u*64 + i])[k] = pk2(w, w);
    }
    // --- zero h buffer 0
    for (int e = tid; e < 512; e += NTHREADS) hb[e] = make_ulonglong2(0ull, 0ull);

    // --- per-thread row constants: packed w_ih and (b_ih + b_hh)
    u64 wih[4], bia[4];
#pragma unroll
    for (int ii = 0; ii < 4; ii++) {
        int i = rg + 16*ii;
        float wv = w_ih[i];
        float bv = b_ih[i] + b_hh[i];
        wih[ii] = pk2(wv, wv);
        bia[ii] = pk2(bv, bv);
    }

    const int p0 = pg, p1 = pg + 8;
    __syncthreads();

    int cur = 0;
    for (int t = 0; t < TT; t++) {
        const int tc = t & (TCH - 1);
        if (tc == 0) {
            // stage x[b0..b0+31][t..t+TCH) packed into batch pairs, [tc][p] layout
            for (int e = tid; e < NB*TCH; e += NTHREADS) {
                int r    = e >> 5;          // local batch 0..31
                int tcol = e & (TCH - 1);
                float v = x[(size_t)(b0 + r)*TT + t + tcol];
                ((float*)xs)[(tcol*NP + (r >> 1))*2 + (r & 1)] = v;
            }
            __syncthreads();
        }

        const ulonglong2* hcur = hb + cur*512;
        ulonglong2*       hnxt = hb + (cur ^ 1)*512;

        u64 xv0 = xs[tc*NP + p0];
        u64 xv1 = xs[tc*NP + p1];

        u64 acc[2][4];
#pragma unroll
        for (int ii = 0; ii < 4; ii++) {
            acc[0][ii] = fma2(wih[ii], xv0, bia[ii]);
            acc[1][ii] = fma2(wih[ii], xv1, bia[ii]);
        }

#pragma unroll 8
        for (int u = 0; u < 32; u++) {
            ulonglong2 h0 = hcur[u*16 + p0];
            ulonglong2 h1 = hcur[u*16 + p1];
#pragma unroll
            for (int ii = 0; ii < 4; ii++) {
                ulonglong2 wv = wb[u*64 + rg + 16*ii];
                acc[0][ii] = fma2(wv.x, h0.x, acc[0][ii]);
                acc[0][ii] = fma2(wv.y, h0.y, acc[0][ii]);
                acc[1][ii] = fma2(wv.x, h1.x, acc[1][ii]);
                acc[1][ii] = fma2(wv.y, h1.y, acc[1][ii]);
            }
        }

        // tanh + store new h
#pragma unroll
        for (int pp = 0; pp < 2; pp++) {
            int p = pg + 8*pp;
#pragma unroll
            for (int ii = 0; ii < 4; ii++) {
                float2 a = up2(acc[pp][ii]);
                u64 hn = pk2(ftanh(a.x), ftanh(a.y));
                int jf = rg + 16*ii;
                ((u64*)&hnxt[(jf >> 1)*16 + p])[jf & 1] = hn;
            }
        }
        __syncthreads();
        cur ^= 1;
    }

    // --- head: out[b, c] = sum_j h[b,j]*w_head[c,j] + b_head[c]
    // final h is in buffer `cur` (== 0 after an even number of steps)
    if (tid < NB) {
        const ulonglong2* hfin = hb + cur*512;
        int p  = tid >> 1;
        int k0 = tid & 1;
        float s[CC];
#pragma unroll
        for (int c = 0; c < CC; c++) s[c] = b_head[c];
        for (int j = 0; j < HH; j++) {
            float2 hv2 = up2(((const u64*)&hfin[(j >> 1)*16 + p])[j & 1]);
            float hv = k0 ? hv2.y : hv2.x;
#pragma unroll
            for (int c = 0; c < CC; c++) s[c] += hv * w_head[c*HH + j];
        }
#pragma unroll
        for (int c = 0; c < CC; c++) out[(size_t)(b0 + tid)*CC + c] = s[c];
    }
}

extern "C" void kernel_launch(void* const* d_in, const int* in_sizes, int n_in,
                              void* d_out, int out_size)
{
    (void)in_sizes; (void)n_in; (void)out_size;
    const float* x      = (const float*)d_in[0];
    const float* w_ih   = (const float*)d_in[1];
    const float* b_ih   = (const float*)d_in[2];
    const float* w_hh   = (const float*)d_in[3];
    const float* b_hh   = (const float*)d_in[4];
    const float* w_head = (const float*)d_in[5];
    const float* b_head = (const float*)d_in[6];
    float* out = (float*)d_out;

    cudaFuncSetAttribute(rnn_f32x2_kernel,
                         cudaFuncAttributeMaxDynamicSharedMemorySize, SMEM_BYTES);
    rnn_f32x2_kernel<<<BB/NB, NTHREADS, SMEM_BYTES>>>(
        x, w_ih, b_ih, w_hh, b_hh, w_head, b_head, out);
}

// round 3
// speedup vs baseline: 1.1054x; 1.1054x over previous
#include <cuda_runtime.h>

// RNN: B=4096, T=1024, H=64, scalar input, C=5 head.
//   h_{t+1}[b,i] = tanh(x[b,t]*w_ih[i] + b_ih[i] + b_hh[i] + sum_j h_t[b,j]*w_hh[i,j])
//   out[b,c]     = sum_j hT[b,j]*w_head[c,j] + b_head[c]
//
// R2 design: f32x2 packed along j (horizontal-add epilogue), natural W/h
// layouts (no duplication), 256 threads/CTA (2 warps/SMSP), padded SMEM
// strides for zero bank conflicts, double-buffered h, 1 barrier/step.

#define BB 4096
#define TT 1024
#define HH 64
#define CC 5
#define NB 32            // batches per CTA
#define NTHREADS 256
#define TCH 32           // x staging chunk (timesteps)
#define WSTRIDE 68       // floats per W row  (bank shift 4/row)
#define HSTRIDE 72       // floats per h row  (bank shift 8/batch)

typedef unsigned long long u64;

__device__ __forceinline__ u64 fma2(u64 a, u64 b, u64 c) {
    u64 d; asm("fma.rn.f32x2 %0, %1, %2, %3;" : "=l"(d) : "l"(a), "l"(b), "l"(c)); return d;
}
__device__ __forceinline__ float2 up2(u64 v) {
    float2 f; asm("mov.b64 {%0,%1}, %2;" : "=f"(f.x), "=f"(f.y) : "l"(v)); return f;
}
__device__ __forceinline__ float ftanh(float xv) {
    // tanh(x) = 1 - 2/(e^{2x}+1); exact at saturation via inf.
    float e = __expf(2.0f * xv);
    return 1.0f - __fdividef(2.0f, e + 1.0f);
}

extern "C" __global__ void __launch_bounds__(NTHREADS, 1)
rnn_jpack_kernel(const float* __restrict__ x,
                 const float* __restrict__ w_ih,
                 const float* __restrict__ b_ih,
                 const float* __restrict__ w_hh,
                 const float* __restrict__ b_hh,
                 const float* __restrict__ w_head,
                 const float* __restrict__ b_head,
                 float* __restrict__ out)
{
    __shared__ __align__(16) float ws[HH * WSTRIDE];      // 17408 B
    __shared__ __align__(16) float hs[2][NB * HSTRIDE];   // 18432 B
    __shared__ float xs[TCH * NB];                        //  4096 B

    const int tid  = threadIdx.x;
    const int b0   = blockIdx.x * NB;
    const int lane = tid & 31;
    const int wrp  = tid >> 5;

    // warp tile: 32 rows x 8 batches; thread tile: 4 rows x 2 batches
    const int bg = lane & 3;               // batch group (4 distinct/warp)
    const int rr = lane >> 2;              // row group   (8 distinct/warp)
    const int warp_row0 = (wrp & 1) * 32;  // 2 row-halves
    const int warp_b0   = (wrp >> 1) * 8;  // 4 batch-groups
    const int bl0 = warp_b0 + bg;          // local batches
    const int bl1 = bl0 + 4;
    const int r0  = warp_row0 + rr;        // rows r0 + {0,8,16,24}

    // --- stage W (natural [row][j], padded stride) ---
    for (int e = tid; e < HH * HH; e += NTHREADS) {
        int i = e >> 6, j = e & 63;
        ws[i * WSTRIDE + j] = w_hh[e];
    }
    // --- zero h buffer 0 ---
    for (int e = tid; e < NB * HSTRIDE; e += NTHREADS) hs[0][e] = 0.0f;

    // --- per-thread row constants ---
    float wihv[4], biasv[4];
#pragma unroll
    for (int ri = 0; ri < 4; ri++) {
        int i = r0 + 8 * ri;
        wihv[ri]  = w_ih[i];
        biasv[ri] = b_ih[i] + b_hh[i];
    }
    __syncthreads();

    // W row pointers (quad-granular)
    const ulonglong2* wq[4];
#pragma unroll
    for (int ri = 0; ri < 4; ri++)
        wq[ri] = (const ulonglong2*)(ws + (r0 + 8 * ri) * WSTRIDE);

    int cur = 0;
    for (int t = 0; t < TT; t++) {
        const int tc = t & (TCH - 1);
        if (tc == 0) {
            // stage x[b0..b0+31][t..t+TCH): coalesced per local batch
            for (int e = tid; e < NB * TCH; e += NTHREADS) {
                int r = e >> 5, tcol = e & (TCH - 1);
                xs[tcol * NB + r] = x[(size_t)(b0 + r) * TT + t + tcol];
            }
            __syncthreads();
        }

        const float* hcur = hs[cur];
        float*       hnxt = hs[cur ^ 1];
        const ulonglong2* hq0 = (const ulonglong2*)(hcur + bl0 * HSTRIDE);
        const ulonglong2* hq1 = (const ulonglong2*)(hcur + bl1 * HSTRIDE);

        const float xb0 = xs[tc * NB + bl0];
        const float xb1 = xs[tc * NB + bl1];

        u64 acc[2][4];
#pragma unroll
        for (int ri = 0; ri < 4; ri++) { acc[0][ri] = 0ull; acc[1][ri] = 0ull; }

#pragma unroll
        for (int q = 0; q < 16; q++) {          // j = 4q .. 4q+3
            ulonglong2 h0 = hq0[q];             // {h[j],h[j+1]},{h[j+2],h[j+3]} b=bl0
            ulonglong2 h1 = hq1[q];
#pragma unroll
            for (int ri = 0; ri < 4; ri++) {
                ulonglong2 wv = wq[ri][q];      // {w[j],w[j+1]},{w[j+2],w[j+3]}
                acc[0][ri] = fma2(wv.x, h0.x, acc[0][ri]);
                acc[1][ri] = fma2(wv.x, h1.x, acc[1][ri]);
                acc[0][ri] = fma2(wv.y, h0.y, acc[0][ri]);
                acc[1][ri] = fma2(wv.y, h1.y, acc[1][ri]);
            }
        }

        // epilogue: horizontal add + input/bias + tanh + store
#pragma unroll
        for (int bi = 0; bi < 2; bi++) {
            const int   bl = bi ? bl1 : bl0;
            const float xb = bi ? xb1 : xb0;
#pragma unroll
            for (int ri = 0; ri < 4; ri++) {
                float2 a = up2(acc[bi][ri]);
                float  s = a.x + a.y + fmaf(xb, wihv[ri], biasv[ri]);
                hnxt[bl * HSTRIDE + r0 + 8 * ri] = ftanh(s);
            }
        }
        __syncthreads();
        cur ^= 1;
    }

    // --- head: out[b,c] = sum_j h[b,j]*w_head[c,j] + b_head[c] ---
    if (tid < NB) {
        const float* hfin = hs[cur] + tid * HSTRIDE;
        float s[CC];
#pragma unroll
        for (int c = 0; c < CC; c++) s[c] = b_head[c];
        for (int j = 0; j < HH; j++) {
            float hv = hfin[j];
#pragma unroll
            for (int c = 0; c < CC; c++) s[c] = fmaf(hv, w_head[c * HH + j], s[c]);
        }
#pragma unroll
        for (int c = 0; c < CC; c++) out[(size_t)(b0 + tid) * CC + c] = s[c];
    }
}

extern "C" void kernel_launch(void* const* d_in, const int* in_sizes, int n_in,
                              void* d_out, int out_size)
{
    (void)in_sizes; (void)n_in; (void)out_size;
    const float* x      = (const float*)d_in[0];
    const float* w_ih   = (const float*)d_in[1];
    const float* b_ih   = (const float*)d_in[2];
    const float* w_hh   = (const float*)d_in[3];
    const float* b_hh   = (const float*)d_in[4];
    const float* w_head = (const float*)d_in[5];
    const float* b_head = (const float*)d_in[6];
    float* out = (float*)d_out;

    rnn_jpack_kernel<<<BB / NB, NTHREADS>>>(
        x, w_ih, b_ih, w_hh, b_hh, w_head, b_head, out);
}